// round 11
// baseline (speedup 1.0000x reference)
#include <cuda_runtime.h>
#include <cuda_fp16.h>
#include <cstdint>

// ===================== problem dims =====================
#define BDIM 4096
#define IDIM 1024
#define HDIM 1024
#define KDIM 2048   // I + H
#define NDIM 4096   // 4 * H, INTERLEAVED: n = j*4 + g  (g in {f,i,o,c})

// ===================== device scratch (static, allowed) =====================
__device__ __align__(256) __half g_A[(size_t)BDIM * KDIM];    // fp16(x|h)
__device__ __align__(256) __half g_W[(size_t)NDIM * KDIM];    // fp16(W), interleaved rows
__device__ __align__(256) float  g_bias[NDIM];                // interleaved j*4+g
__device__ __align__(256) float  g_mask[BDIM];

// ===================== small PTX helpers (sm_80+ features only) =====================
__device__ __forceinline__ uint32_t smem_to_u32(const void* p) {
    uint32_t a;
    asm("{ .reg .u64 t; cvta.to.shared.u64 t, %1; cvt.u32.u64 %0, t; }" : "=r"(a) : "l"(p));
    return a;
}

__device__ __forceinline__ void cp16(uint32_t saddr, const void* g) {
    asm volatile("cp.async.cg.shared.global [%0], [%1], 16;" :: "r"(saddr), "l"(g) : "memory");
}

#define CP_COMMIT() asm volatile("cp.async.commit_group;" ::: "memory")
#define CP_WAIT(N)  asm volatile("cp.async.wait_group %0;" :: "n"(N) : "memory")

__device__ __forceinline__ void ldsm4(uint32_t* r, uint32_t addr) {
    asm volatile("ldmatrix.sync.aligned.m8n8.x4.shared.b16 {%0,%1,%2,%3}, [%4];"
                 : "=r"(r[0]), "=r"(r[1]), "=r"(r[2]), "=r"(r[3]) : "r"(addr));
}

__device__ __forceinline__ void mma16816(float* c, const uint32_t* a, uint32_t b0, uint32_t b1) {
    asm volatile(
        "mma.sync.aligned.m16n8k16.row.col.f32.f16.f16.f32 "
        "{%0,%1,%2,%3}, {%4,%5,%6,%7}, {%8,%9}, {%0,%1,%2,%3};"
        : "+f"(c[0]), "+f"(c[1]), "+f"(c[2]), "+f"(c[3])
        : "r"(a[0]), "r"(a[1]), "r"(a[2]), "r"(a[3]), "r"(b0), "r"(b1));
}

// ===================== conversion helpers =====================
__device__ __forceinline__ uint32_t pkh2(__half a, __half b) {
    __half2 t = __halves2half2(a, b);
    return *reinterpret_cast<uint32_t*>(&t);
}

// store 4 fp16 and return sum of squares
__device__ __forceinline__ float h_store4(float4 v, __half* dst) {
    uint2 hv = make_uint2(pkh2(__float2half_rn(v.x), __float2half_rn(v.y)),
                          pkh2(__float2half_rn(v.z), __float2half_rn(v.w)));
    *reinterpret_cast<uint2*>(dst) = hv;
    return v.x * v.x + v.y * v.y + v.z * v.z + v.w * v.w;
}

// ===================== kernel 1: convert A = [x | h_prev] + silence mask =====================
__global__ void convert_A_kernel(const float* __restrict__ x, const float* __restrict__ h) {
    int m = blockIdx.x;
    int t = threadIdx.x;  // 256
    float4 vx = reinterpret_cast<const float4*>(x)[(size_t)m * 256 + t];
    float ss = h_store4(vx, g_A + (size_t)m * KDIM + 4 * t);
    float4 vh = reinterpret_cast<const float4*>(h)[(size_t)m * 256 + t];
    h_store4(vh, g_A + (size_t)m * KDIM + IDIM + 4 * t);

    __shared__ float red[256];
    red[t] = ss;
    __syncthreads();
    for (int s = 128; s > 0; s >>= 1) {
        if (t < s) red[t] += red[t + s];
        __syncthreads();
    }
    if (t == 0) g_mask[m] = (red[0] > 1e-6f) ? 1.0f : 0.0f;  // norm > 0.001
}

// ===================== kernel 2: convert packed weights (interleaved rows, fp16) ==========
__global__ void convert_W_kernel(const float* __restrict__ Wf, const float* __restrict__ Wi,
                                 const float* __restrict__ Wo, const float* __restrict__ Wc,
                                 const float* __restrict__ Vf, const float* __restrict__ Vi,
                                 const float* __restrict__ Vo, const float* __restrict__ Vc) {
    int n = blockIdx.x;     // 0..4095 (gate-major source index)
    int t = threadIdx.x;    // 256
    int g = n >> 10, j = n & 1023;
    int row = (j << 2) | g;  // interleaved destination row
    const float* W = (g == 0) ? Wf : (g == 1) ? Wi : (g == 2) ? Wo : Wc;
    const float* V = (g == 0) ? Vf : (g == 1) ? Vi : (g == 2) ? Vo : Vc;
    float4 vw = reinterpret_cast<const float4*>(W)[(size_t)j * 256 + t];
    h_store4(vw, g_W + (size_t)row * KDIM + 4 * t);
    float4 vv = reinterpret_cast<const float4*>(V)[(size_t)j * 256 + t];
    h_store4(vv, g_W + (size_t)row * KDIM + IDIM + 4 * t);
}

// ===================== kernel 3: combined bias (interleaved) =====================
__global__ void bias_kernel(const float* __restrict__ bWf, const float* __restrict__ bVf, const float* __restrict__ bf_,
                            const float* __restrict__ bWi, const float* __restrict__ bVi, const float* __restrict__ bi_,
                            const float* __restrict__ bWo, const float* __restrict__ bVo, const float* __restrict__ bo_,
                            const float* __restrict__ bWc, const float* __restrict__ bVc, const float* __restrict__ bc_) {
    int n = blockIdx.x * blockDim.x + threadIdx.x;
    if (n >= NDIM) return;
    int g = n >> 10, j = n & 1023;
    const float* a = (g == 0) ? bWf : (g == 1) ? bWi : (g == 2) ? bWo : bWc;
    const float* b = (g == 0) ? bVf : (g == 1) ? bVi : (g == 2) ? bVo : bVc;
    const float* c = (g == 0) ? bf_ : (g == 1) ? bi_ : (g == 2) ? bo_ : bc_;
    g_bias[(j << 2) | g] = a[j] + b[j] + c[j];
}

// ===================== kernel 4: pipelined GEMM + fused LSTM epilogue =====================
// gates = A*W^T  (fp16 inputs, fp32 accum), then activations -> out
// 128 threads, 4 warps in 2x2 grid, warp tile 64x64 (high ILP, 4:1 mma:ldsm)
#define NTHREADS 128
#define BM 128
#define BN 128
#define BK 32
#define NK (KDIM / BK)          // 64 k-tiles
#define TOTAL_TILES 1024
#define GRID_CTAS 888           // persistent; 136 CTAs do 2 tiles
#define BUF_BYTES (128 * 64)    // 8192: 128 rows x 64B (pitch 64, swizzled)
#define STAGE_BYTES (2 * BUF_BYTES)    // 16384: A, W
#define NSTAGES 4
#define EPITCH 132              // floats per gates row in smem epilogue
#define GEMM_SMEM (128 * EPITCH * 4)   // 67584 >= NSTAGES*STAGE_BYTES (65536)

// swizzled byte offset of 16B chunk c (0..3) in row r, pitch 64.
// swz(r+16, c) == swz(r, c) + 1024 (swizzle term invariant under r += 16).
__device__ __forceinline__ uint32_t swz(int r, int c) {
    return (uint32_t)(r * 64 + ((c ^ ((r >> 1) & 3)) << 4));
}

__global__ void __launch_bounds__(NTHREADS, 2) gemm_kernel(const float* __restrict__ c_prev,
                                                           float* __restrict__ out, int n_out) {
    extern __shared__ char smem[];
    uint32_t sb = smem_to_u32(smem);
    int tid = threadIdx.x, wid = tid >> 5, lid = tid & 31;
    int wm = (wid >> 1) * 64;   // 2x2 warp grid, warp tile 64x64
    int wn = (wid & 1) * 64;
    int lrow = lid & 15;
    int cbase = lid >> 4;       // 0 or 1: second 16B chunk within k16-step

    // ---- thread-invariant ldmatrix base offsets, one per k16-step (2 per BK=32)
    uint32_t offA0[2], offW0[2];
    #pragma unroll
    for (int ks = 0; ks < 2; ++ks) {
        int cidx = ks * 2 + cbase;
        offA0[ks] = swz(wm + lrow, cidx);                       // A buffer at 0
        offW0[ks] = swz(wn + lrow, cidx) + (uint32_t)BUF_BYTES; // W buffer at +BUF
    }

    // ---- thread-invariant cp.async producer offsets (128 threads x 4 chunks = 512 = 128 rows x 4)
    uint32_t ls_soff[4];
    size_t   ls_goff[4];
    #pragma unroll
    for (int i = 0; i < 4; ++i) {
        int q = tid + i * NTHREADS;
        int r = q >> 2, c = q & 3;
        ls_soff[i] = swz(r, c);
        ls_goff[i] = (size_t)r * KDIM + c * 8;
    }

    for (int t = blockIdx.x; t < TOTAL_TILES; t += GRID_CTAS) {
        int m0 = (t >> 5) * BM;
        int n0 = (t & 31) * BN;
        int j_base = n0 >> 2;   // interleaved: 32 j's per CTA tile

        const __half* pA = g_A + (size_t)m0 * KDIM;
        const __half* pW = g_W + (size_t)n0 * KDIM;

        #define LOAD_STAGE(stage, kt) do {                                      \
            uint32_t s0_ = sb + (uint32_t)(stage) * STAGE_BYTES;                \
            int k0_ = (kt) * BK;                                                \
            cp16(s0_ + ls_soff[0],             pA + k0_ + ls_goff[0]);          \
            cp16(s0_ + ls_soff[1],             pA + k0_ + ls_goff[1]);          \
            cp16(s0_ + ls_soff[2],             pA + k0_ + ls_goff[2]);          \
            cp16(s0_ + ls_soff[3],             pA + k0_ + ls_goff[3]);          \
            cp16(s0_ + BUF_BYTES + ls_soff[0], pW + k0_ + ls_goff[0]);          \
            cp16(s0_ + BUF_BYTES + ls_soff[1], pW + k0_ + ls_goff[1]);          \
            cp16(s0_ + BUF_BYTES + ls_soff[2], pW + k0_ + ls_goff[2]);          \
            cp16(s0_ + BUF_BYTES + ls_soff[3], pW + k0_ + ls_goff[3]);          \
            CP_COMMIT();                                                        \
        } while (0)

        float acc[4][8][4];
        #pragma unroll
        for (int i = 0; i < 4; ++i)
            #pragma unroll
            for (int j = 0; j < 8; ++j)
                #pragma unroll
                for (int k = 0; k < 4; ++k) acc[i][j][k] = 0.0f;

        // prologue: stages 0,1,2 (prefetch distance 3)
        LOAD_STAGE(0, 0);
        LOAD_STAGE(1, 1);
        LOAD_STAGE(2, 2);

        for (int kt = 0; kt < NK; ++kt) {
            if (kt < NK - 2)       { CP_WAIT(2); }
            else if (kt == NK - 2) { CP_WAIT(1); }
            else                   { CP_WAIT(0); }
            __syncthreads();   // tile kt visible to all; frees buffer (kt+3)%4

            uint32_t cur = sb + (uint32_t)(kt & (NSTAGES - 1)) * STAGE_BYTES;

            #pragma unroll
            for (int ks = 0; ks < 2; ++ks) {
                uint32_t aB = cur + offA0[ks];   // A fragment base (64 rows = 4 frags)
                uint32_t wB = cur + offW0[ks];   // W fragment base (64 cols = 4 frags)

                uint32_t a[4][4], w0[4][4];
                #pragma unroll
                for (int am = 0; am < 4; ++am)
                    ldsm4(a[am], aB + (uint32_t)(am * 1024));
                #pragma unroll
                for (int bt = 0; bt < 4; ++bt)
                    ldsm4(w0[bt], wB + (uint32_t)(bt * 1024));

                #pragma unroll
                for (int am = 0; am < 4; ++am)
                    #pragma unroll
                    for (int bt = 0; bt < 4; ++bt) {
                        mma16816(acc[am][2 * bt],     a[am], w0[bt][0], w0[bt][2]);
                        mma16816(acc[am][2 * bt + 1], a[am], w0[bt][1], w0[bt][3]);
                    }
            }

            // prefetch tile kt+3 (top barrier of next iter protects WAR)
            if (kt + 3 < NK)
                LOAD_STAGE((kt + 3) & (NSTAGES - 1), kt + 3);
        }
        #undef LOAD_STAGE

        // ===== fused epilogue: acc -> smem -> activations -> out =====
        __syncthreads();   // done reading stage buffers; reuse smem for gates
        float* sg = reinterpret_cast<float*>(smem);   // [128][EPITCH]
        int gid = lid >> 2, tig = lid & 3;
        #pragma unroll
        for (int am = 0; am < 4; ++am) {
            #pragma unroll
            for (int bn = 0; bn < 8; ++bn) {
                const float* c = acc[am][bn];
                int row = wm + am * 16 + gid;
                int col = wn + bn * 8 + tig * 2;
                sg[row * EPITCH + col]           = c[0];
                sg[row * EPITCH + col + 1]       = c[1];
                sg[(row + 8) * EPITCH + col]     = c[2];
                sg[(row + 8) * EPITCH + col + 1] = c[3];
            }
        }
        __syncthreads();

        const int BH = BDIM * HDIM;
        #pragma unroll
        for (int i = 0; i < 32; ++i) {
            int idx = tid + i * NTHREADS;   // 128 rows x 32 j
            int row = idx >> 5, lj = idx & 31;
            float4 gv = *reinterpret_cast<const float4*>(&sg[row * EPITCH + lj * 4]);
            int jg = j_base + lj;
            float4 bv = *reinterpret_cast<const float4*>(&g_bias[jg * 4]);
            float fp = gv.x + bv.x, ip = gv.y + bv.y, op = gv.z + bv.z, cp = gv.w + bv.w;
            float ft = 1.0f / (1.0f + expf(-fp));
            float it = 1.0f / (1.0f + expf(-ip));
            float ot = 1.0f / (1.0f + expf(-op));
            float ct = tanhf(cp);
            int m = m0 + row;
            int oidx = m * HDIM + jg;
            float cpv = c_prev[oidx];
            float cn = ft * cpv + it * cpv + g_mask[m] * (it * ct);
            float hn = ot * tanhf(cn);
            out[oidx] = hn;
            if (BH + oidx < n_out)     out[BH + oidx] = cn;
            if (2 * BH + oidx < n_out) out[2 * BH + oidx] = ct;
        }
        __syncthreads();   // epilogue reads done before next tile's cp.async writes
    }
}

// ===================== launcher =====================
extern "C" void kernel_launch(void* const* d_in, const int* in_sizes, int n_in,
                              void* d_out, int out_size) {
    (void)n_in;
    const float* x      = (const float*)d_in[0];
    const float* h_prev = (const float*)d_in[1];
    const float* c_prev = (const float*)d_in[2];
    // d_in[3] = c_prev_tilde_dummy (unused)

    // Input order detection (dict order vs signature order); see round-2 notes.
    const float *W[4], *V[4], *bW[4], *bV[4], *bx[4];
    if (in_sizes[8] > 100000) {
        for (int g = 0; g < 4; ++g) {   // dict order
            W[g]  = (const float*)d_in[4 + 4 * g];
            bW[g] = (const float*)d_in[5 + 4 * g];
            V[g]  = (const float*)d_in[6 + 4 * g];
            bV[g] = (const float*)d_in[7 + 4 * g];
            bx[g] = (const float*)d_in[20 + g];
        }
    } else {
        for (int g = 0; g < 4; ++g) {   // signature order
            W[g]  = (const float*)d_in[4 + 5 * g];
            bW[g] = (const float*)d_in[5 + 5 * g];
            V[g]  = (const float*)d_in[6 + 5 * g];
            bV[g] = (const float*)d_in[7 + 5 * g];
            bx[g] = (const float*)d_in[8 + 5 * g];
        }
    }

    convert_A_kernel<<<BDIM, 256>>>(x, h_prev);
    convert_W_kernel<<<NDIM, 256>>>(W[0], W[1], W[2], W[3], V[0], V[1], V[2], V[3]);
    bias_kernel<<<NDIM / 256, 256>>>(bW[0], bV[0], bx[0], bW[1], bV[1], bx[1],
                                     bW[2], bV[2], bx[2], bW[3], bV[3], bx[3]);

    cudaFuncSetAttribute(gemm_kernel, cudaFuncAttributeMaxDynamicSharedMemorySize,
                         (int)GEMM_SMEM);
    gemm_kernel<<<GRID_CTAS, NTHREADS, GEMM_SMEM>>>(c_prev, (float*)d_out, out_size);
}

// round 12
// speedup vs baseline: 1.0294x; 1.0294x over previous
#include <cuda_runtime.h>
#include <cuda_fp16.h>
#include <cstdint>

// ===================== problem dims =====================
#define BDIM 4096
#define IDIM 1024
#define HDIM 1024
#define KDIM 2048   // I + H
#define NDIM 4096   // 4 * H, INTERLEAVED: n = j*4 + g  (g in {f,i,o,c})

// ===================== device scratch (static, allowed) =====================
__device__ __align__(256) __half g_A[(size_t)BDIM * KDIM];    // fp16(x|h)
__device__ __align__(256) __half g_W[(size_t)NDIM * KDIM];    // fp16(W), interleaved rows
__device__ __align__(256) float  g_bias[NDIM];                // interleaved j*4+g
__device__ __align__(256) float  g_mask[BDIM];

// ===================== small PTX helpers (sm_80+ features only) =====================
__device__ __forceinline__ uint32_t smem_to_u32(const void* p) {
    uint32_t a;
    asm("{ .reg .u64 t; cvta.to.shared.u64 t, %1; cvt.u32.u64 %0, t; }" : "=r"(a) : "l"(p));
    return a;
}

__device__ __forceinline__ void cp16(uint32_t saddr, const void* g) {
    asm volatile("cp.async.cg.shared.global [%0], [%1], 16;" :: "r"(saddr), "l"(g) : "memory");
}

#define CP_COMMIT() asm volatile("cp.async.commit_group;" ::: "memory")
#define CP_WAIT(N)  asm volatile("cp.async.wait_group %0;" :: "n"(N) : "memory")

__device__ __forceinline__ void ldsm4(uint32_t* r, uint32_t addr) {
    asm volatile("ldmatrix.sync.aligned.m8n8.x4.shared.b16 {%0,%1,%2,%3}, [%4];"
                 : "=r"(r[0]), "=r"(r[1]), "=r"(r[2]), "=r"(r[3]) : "r"(addr));
}

__device__ __forceinline__ void mma16816(float* c, const uint32_t* a, uint32_t b0, uint32_t b1) {
    asm volatile(
        "mma.sync.aligned.m16n8k16.row.col.f32.f16.f16.f32 "
        "{%0,%1,%2,%3}, {%4,%5,%6,%7}, {%8,%9}, {%0,%1,%2,%3};"
        : "+f"(c[0]), "+f"(c[1]), "+f"(c[2]), "+f"(c[3])
        : "r"(a[0]), "r"(a[1]), "r"(a[2]), "r"(a[3]), "r"(b0), "r"(b1));
}

// ===================== conversion helpers =====================
__device__ __forceinline__ uint32_t pkh2(__half a, __half b) {
    __half2 t = __halves2half2(a, b);
    return *reinterpret_cast<uint32_t*>(&t);
}

// store 4 fp16 and return sum of squares
__device__ __forceinline__ float h_store4(float4 v, __half* dst) {
    uint2 hv = make_uint2(pkh2(__float2half_rn(v.x), __float2half_rn(v.y)),
                          pkh2(__float2half_rn(v.z), __float2half_rn(v.w)));
    *reinterpret_cast<uint2*>(dst) = hv;
    return v.x * v.x + v.y * v.y + v.z * v.z + v.w * v.w;
}

// ===================== kernel 1: convert A = [x | h_prev] + silence mask =====================
__global__ void convert_A_kernel(const float* __restrict__ x, const float* __restrict__ h) {
    int m = blockIdx.x;
    int t = threadIdx.x;  // 256
    float4 vx = reinterpret_cast<const float4*>(x)[(size_t)m * 256 + t];
    float ss = h_store4(vx, g_A + (size_t)m * KDIM + 4 * t);
    float4 vh = reinterpret_cast<const float4*>(h)[(size_t)m * 256 + t];
    h_store4(vh, g_A + (size_t)m * KDIM + IDIM + 4 * t);

    __shared__ float red[256];
    red[t] = ss;
    __syncthreads();
    for (int s = 128; s > 0; s >>= 1) {
        if (t < s) red[t] += red[t + s];
        __syncthreads();
    }
    if (t == 0) g_mask[m] = (red[0] > 1e-6f) ? 1.0f : 0.0f;  // norm > 0.001
}

// ===================== kernel 2: convert packed weights (interleaved rows, fp16) ==========
__global__ void convert_W_kernel(const float* __restrict__ Wf, const float* __restrict__ Wi,
                                 const float* __restrict__ Wo, const float* __restrict__ Wc,
                                 const float* __restrict__ Vf, const float* __restrict__ Vi,
                                 const float* __restrict__ Vo, const float* __restrict__ Vc) {
    int n = blockIdx.x;     // 0..4095 (gate-major source index)
    int t = threadIdx.x;    // 256
    int g = n >> 10, j = n & 1023;
    int row = (j << 2) | g;  // interleaved destination row
    const float* W = (g == 0) ? Wf : (g == 1) ? Wi : (g == 2) ? Wo : Wc;
    const float* V = (g == 0) ? Vf : (g == 1) ? Vi : (g == 2) ? Vo : Vc;
    float4 vw = reinterpret_cast<const float4*>(W)[(size_t)j * 256 + t];
    h_store4(vw, g_W + (size_t)row * KDIM + 4 * t);
    float4 vv = reinterpret_cast<const float4*>(V)[(size_t)j * 256 + t];
    h_store4(vv, g_W + (size_t)row * KDIM + IDIM + 4 * t);
}

// ===================== kernel 3: combined bias (interleaved) =====================
__global__ void bias_kernel(const float* __restrict__ bWf, const float* __restrict__ bVf, const float* __restrict__ bf_,
                            const float* __restrict__ bWi, const float* __restrict__ bVi, const float* __restrict__ bi_,
                            const float* __restrict__ bWo, const float* __restrict__ bVo, const float* __restrict__ bo_,
                            const float* __restrict__ bWc, const float* __restrict__ bVc, const float* __restrict__ bc_) {
    int n = blockIdx.x * blockDim.x + threadIdx.x;
    if (n >= NDIM) return;
    int g = n >> 10, j = n & 1023;
    const float* a = (g == 0) ? bWf : (g == 1) ? bWi : (g == 2) ? bWo : bWc;
    const float* b = (g == 0) ? bVf : (g == 1) ? bVi : (g == 2) ? bVo : bVc;
    const float* c = (g == 0) ? bf_ : (g == 1) ? bi_ : (g == 2) ? bo_ : bc_;
    g_bias[(j << 2) | g] = a[j] + b[j] + c[j];
}

// ===================== kernel 4: pipelined GEMM + fused LSTM epilogue =====================
// gates = A*W^T  (fp16 inputs, fp32 accum), then activations -> out
// 128 threads, 2x2 warp grid, warp tile 64x64, REGISTER-DOUBLE-BUFFERED fragments:
// ldsm for k-step s+1 issues before the 32 MMAs of step s -> tensor pipe never
// waits on shared-memory latency.
#define NTHREADS 128
#define BM 128
#define BN 128
#define BK 32
#define NK (KDIM / BK)          // 64 k-tiles
#define TOTAL_TILES 1024
#define GRID_CTAS 888           // persistent; 136 CTAs do 2 tiles
#define BUF_BYTES (128 * 64)    // 8192: 128 rows x 64B (pitch 64, swizzled)
#define STAGE_BYTES (2 * BUF_BYTES)    // 16384: A, W
#define NSTAGES 4
#define EPITCH 132              // floats per gates row in smem epilogue
#define GEMM_SMEM (128 * EPITCH * 4)   // 67584 >= NSTAGES*STAGE_BYTES (65536)

// swizzled byte offset of 16B chunk c (0..3) in row r, pitch 64.
// swz(r+16, c) == swz(r, c) + 1024 (swizzle term invariant under r += 16).
__device__ __forceinline__ uint32_t swz(int r, int c) {
    return (uint32_t)(r * 64 + ((c ^ ((r >> 1) & 3)) << 4));
}

// load one warp's fragment set (64 rows A, 64 rows W for one k16 step)
__device__ __forceinline__ void load_frags(uint32_t stage_base, uint32_t offA, uint32_t offW,
                                           uint32_t a[4][4], uint32_t w[4][4]) {
    uint32_t aB = stage_base + offA;
    uint32_t wB = stage_base + offW;
    #pragma unroll
    for (int am = 0; am < 4; ++am) ldsm4(a[am], aB + (uint32_t)(am * 1024));
    #pragma unroll
    for (int bt = 0; bt < 4; ++bt) ldsm4(w[bt], wB + (uint32_t)(bt * 1024));
}

// 32 independent MMAs on one fragment set
__device__ __forceinline__ void do_mma(float acc[4][8][4], uint32_t a[4][4], uint32_t w[4][4]) {
    #pragma unroll
    for (int am = 0; am < 4; ++am)
        #pragma unroll
        for (int bt = 0; bt < 4; ++bt) {
            mma16816(acc[am][2 * bt],     a[am], w[bt][0], w[bt][2]);
            mma16816(acc[am][2 * bt + 1], a[am], w[bt][1], w[bt][3]);
        }
}

__global__ void __launch_bounds__(NTHREADS, 2) gemm_kernel(const float* __restrict__ c_prev,
                                                           float* __restrict__ out, int n_out) {
    extern __shared__ char smem[];
    uint32_t sb = smem_to_u32(smem);
    int tid = threadIdx.x, wid = tid >> 5, lid = tid & 31;
    int wm = (wid >> 1) * 64;   // 2x2 warp grid, warp tile 64x64
    int wn = (wid & 1) * 64;
    int lrow = lid & 15;
    int cbase = lid >> 4;       // 0 or 1: second 16B chunk within k16-step

    // ---- thread-invariant ldmatrix base offsets, one per k16-step (2 per BK=32)
    uint32_t offA0[2], offW0[2];
    #pragma unroll
    for (int ks = 0; ks < 2; ++ks) {
        int cidx = ks * 2 + cbase;
        offA0[ks] = swz(wm + lrow, cidx);                       // A buffer at 0
        offW0[ks] = swz(wn + lrow, cidx) + (uint32_t)BUF_BYTES; // W buffer at +BUF
    }

    // ---- thread-invariant cp.async producer offsets (128 threads x 4 chunks = 128 rows x 4)
    uint32_t ls_soff[4], ls_goff[4];
    #pragma unroll
    for (int i = 0; i < 4; ++i) {
        int q = tid + i * NTHREADS;
        int r = q >> 2, c = q & 3;
        ls_soff[i] = swz(r, c);
        ls_goff[i] = (uint32_t)(r * KDIM + c * 8);
    }

    for (int t = blockIdx.x; t < TOTAL_TILES; t += GRID_CTAS) {
        int m0 = (t >> 5) * BM;
        int n0 = (t & 31) * BN;
        int j_base = n0 >> 2;   // interleaved: 32 j's per CTA tile

        const __half* pA = g_A + (size_t)m0 * KDIM;
        const __half* pW = g_W + (size_t)n0 * KDIM;

        #define LOAD_STAGE(stage, kt) do {                                      \
            uint32_t s0_ = sb + (uint32_t)(stage) * STAGE_BYTES;                \
            uint32_t k0_ = (uint32_t)((kt) * BK);                               \
            cp16(s0_ + ls_soff[0],             pA + k0_ + ls_goff[0]);          \
            cp16(s0_ + ls_soff[1],             pA + k0_ + ls_goff[1]);          \
            cp16(s0_ + ls_soff[2],             pA + k0_ + ls_goff[2]);          \
            cp16(s0_ + ls_soff[3],             pA + k0_ + ls_goff[3]);          \
            cp16(s0_ + BUF_BYTES + ls_soff[0], pW + k0_ + ls_goff[0]);          \
            cp16(s0_ + BUF_BYTES + ls_soff[1], pW + k0_ + ls_goff[1]);          \
            cp16(s0_ + BUF_BYTES + ls_soff[2], pW + k0_ + ls_goff[2]);          \
            cp16(s0_ + BUF_BYTES + ls_soff[3], pW + k0_ + ls_goff[3]);          \
            CP_COMMIT();                                                        \
        } while (0)

        float acc[4][8][4];
        #pragma unroll
        for (int i = 0; i < 4; ++i)
            #pragma unroll
            for (int j = 0; j < 8; ++j)
                #pragma unroll
                for (int k = 0; k < 4; ++k) acc[i][j][k] = 0.0f;

        // prologue: stages 0,1,2 in flight; stages 0,1 complete+visible; preload frags(0,ks0)
        LOAD_STAGE(0, 0);
        LOAD_STAGE(1, 1);
        LOAD_STAGE(2, 2);
        CP_WAIT(1);
        __syncthreads();

        uint32_t a[2][4][4], w[2][4][4];   // double-buffered fragment sets
        load_frags(sb, offA0[0], offW0[0], a[0], w[0]);

        #pragma unroll 1
        for (int kt = 0; kt < NK; ++kt) {
            uint32_t cur = sb + (uint32_t)(kt & (NSTAGES - 1)) * STAGE_BYTES;
            uint32_t nxt = sb + (uint32_t)((kt + 1) & (NSTAGES - 1)) * STAGE_BYTES;
            int pb = kt & 1 ? 0 : 0;   // buffer parity handled explicitly below
            (void)pb;

            // ks = 0: prefetch (cur, ks1) frags, then mma current set.
            // Buffer roles alternate every ks; with 2 ks per kt the kt-entry
            // buffer is always a[0]/w[0].
            load_frags(cur, offA0[1], offW0[1], a[1], w[1]);
            do_mma(acc, a[0], w[0]);

            // ks = 1: prefetch (kt+1, ks0) frags (stage kt+1 is visible: end-of-
            // previous-iter CP_WAIT(1)+sync guaranteed it), then mma.
            if (kt + 1 < NK)
                load_frags(nxt, offA0[0], offW0[0], a[0], w[0]);
            do_mma(acc, a[1], w[1]);

            // issue prefetch for tile kt+3 (overwrites stage (kt-1)%4: last read
            // by ldsm at iter kt-2, barrier since)
            if (kt + 3 < NK)
                LOAD_STAGE((kt + 3) & (NSTAGES - 1), kt + 3);
            if (kt + 1 < NK) {
                CP_WAIT(1);       // stages <= kt+2 complete
                __syncthreads();  // ... and CTA-visible; frees stage (kt+4)%4 writes
            }
        }
        #undef LOAD_STAGE

        // ===== fused epilogue: acc -> smem -> activations -> out =====
        __syncthreads();   // all warps done with stage buffers; reuse smem for gates
        float* sg = reinterpret_cast<float*>(smem);   // [128][EPITCH]
        int gid = lid >> 2, tig = lid & 3;
        #pragma unroll
        for (int am = 0; am < 4; ++am) {
            #pragma unroll
            for (int bn = 0; bn < 8; ++bn) {
                const float* c = acc[am][bn];
                int row = wm + am * 16 + gid;
                int col = wn + bn * 8 + tig * 2;
                sg[row * EPITCH + col]           = c[0];
                sg[row * EPITCH + col + 1]       = c[1];
                sg[(row + 8) * EPITCH + col]     = c[2];
                sg[(row + 8) * EPITCH + col + 1] = c[3];
            }
        }
        __syncthreads();

        const int BH = BDIM * HDIM;
        #pragma unroll
        for (int i = 0; i < 32; ++i) {
            int idx = tid + i * NTHREADS;   // 128 rows x 32 j
            int row = idx >> 5, lj = idx & 31;
            float4 gv = *reinterpret_cast<const float4*>(&sg[row * EPITCH + lj * 4]);
            int jg = j_base + lj;
            float4 bv = *reinterpret_cast<const float4*>(&g_bias[jg * 4]);
            float fp = gv.x + bv.x, ip = gv.y + bv.y, op = gv.z + bv.z, cp = gv.w + bv.w;
            float ft = 1.0f / (1.0f + expf(-fp));
            float it = 1.0f / (1.0f + expf(-ip));
            float ot = 1.0f / (1.0f + expf(-op));
            float ct = tanhf(cp);
            int m = m0 + row;
            int oidx = m * HDIM + jg;
            float cpv = c_prev[oidx];
            float cn = ft * cpv + it * cpv + g_mask[m] * (it * ct);
            float hn = ot * tanhf(cn);
            out[oidx] = hn;
            if (BH + oidx < n_out)     out[BH + oidx] = cn;
            if (2 * BH + oidx < n_out) out[2 * BH + oidx] = ct;
        }
        __syncthreads();   // epilogue reads done before next tile's cp.async writes
    }
}

// ===================== launcher =====================
extern "C" void kernel_launch(void* const* d_in, const int* in_sizes, int n_in,
                              void* d_out, int out_size) {
    (void)n_in;
    const float* x      = (const float*)d_in[0];
    const float* h_prev = (const float*)d_in[1];
    const float* c_prev = (const float*)d_in[2];
    // d_in[3] = c_prev_tilde_dummy (unused)

    // Input order detection (dict order vs signature order); see round-2 notes.
    const float *W[4], *V[4], *bW[4], *bV[4], *bx[4];
    if (in_sizes[8] > 100000) {
        for (int g = 0; g < 4; ++g) {   // dict order
            W[g]  = (const float*)d_in[4 + 4 * g];
            bW[g] = (const float*)d_in[5 + 4 * g];
            V[g]  = (const float*)d_in[6 + 4 * g];
            bV[g] = (const float*)d_in[7 + 4 * g];
            bx[g] = (const float*)d_in[20 + g];
        }
    } else {
        for (int g = 0; g < 4; ++g) {   // signature order
            W[g]  = (const float*)d_in[4 + 5 * g];
            bW[g] = (const float*)d_in[5 + 5 * g];
            V[g]  = (const float*)d_in[6 + 5 * g];
            bV[g] = (const float*)d_in[7 + 5 * g];
            bx[g] = (const float*)d_in[8 + 5 * g];
        }
    }

    convert_A_kernel<<<BDIM, 256>>>(x, h_prev);
    convert_W_kernel<<<NDIM, 256>>>(W[0], W[1], W[2], W[3], V[0], V[1], V[2], V[3]);
    bias_kernel<<<NDIM / 256, 256>>>(bW[0], bV[0], bx[0], bW[1], bV[1], bx[1],
                                     bW[2], bV[2], bx[2], bW[3], bV[3], bx[3]);

    cudaFuncSetAttribute(gemm_kernel, cudaFuncAttributeMaxDynamicSharedMemorySize,
                         (int)GEMM_SMEM);
    gemm_kernel<<<GRID_CTAS, NTHREADS, GEMM_SMEM>>>(c_prev, (float*)d_out, out_size);
}

// round 13
// speedup vs baseline: 1.1265x; 1.0943x over previous
#include <cuda_runtime.h>
#include <cuda_fp16.h>
#include <cstdint>

// ===================== problem dims =====================
#define BDIM 4096
#define IDIM 1024
#define HDIM 1024
#define KDIM 2048   // I + H
#define NDIM 4096   // 4 * H, INTERLEAVED: n = j*4 + g  (g in {f,i,o,c})

// ===================== device scratch (static, allowed) =====================
__device__ __align__(256) __half g_A[(size_t)BDIM * KDIM];    // fp16(x|h)
__device__ __align__(256) __half g_W[(size_t)NDIM * KDIM];    // fp16(W), interleaved rows
__device__ __align__(256) float  g_bias[NDIM];                // interleaved j*4+g
__device__ __align__(256) float  g_mask[BDIM];

// ===================== small PTX helpers (sm_80+ features only) =====================
__device__ __forceinline__ uint32_t smem_to_u32(const void* p) {
    uint32_t a;
    asm("{ .reg .u64 t; cvta.to.shared.u64 t, %1; cvt.u32.u64 %0, t; }" : "=r"(a) : "l"(p));
    return a;
}

__device__ __forceinline__ void cp16(uint32_t saddr, const void* g) {
    asm volatile("cp.async.cg.shared.global [%0], [%1], 16;" :: "r"(saddr), "l"(g) : "memory");
}

#define CP_COMMIT() asm volatile("cp.async.commit_group;" ::: "memory")
#define CP_WAIT(N)  asm volatile("cp.async.wait_group %0;" :: "n"(N) : "memory")

__device__ __forceinline__ void ldsm4(uint32_t* r, uint32_t addr) {
    asm volatile("ldmatrix.sync.aligned.m8n8.x4.shared.b16 {%0,%1,%2,%3}, [%4];"
                 : "=r"(r[0]), "=r"(r[1]), "=r"(r[2]), "=r"(r[3]) : "r"(addr));
}

__device__ __forceinline__ void mma16816(float* c, const uint32_t* a, uint32_t b0, uint32_t b1) {
    asm volatile(
        "mma.sync.aligned.m16n8k16.row.col.f32.f16.f16.f32 "
        "{%0,%1,%2,%3}, {%4,%5,%6,%7}, {%8,%9}, {%0,%1,%2,%3};"
        : "+f"(c[0]), "+f"(c[1]), "+f"(c[2]), "+f"(c[3])
        : "r"(a[0]), "r"(a[1]), "r"(a[2]), "r"(a[3]), "r"(b0), "r"(b1));
}

// ===================== conversion helpers =====================
__device__ __forceinline__ uint32_t pkh2(__half a, __half b) {
    __half2 t = __halves2half2(a, b);
    return *reinterpret_cast<uint32_t*>(&t);
}

// store 4 fp16 and return sum of squares
__device__ __forceinline__ float h_store4(float4 v, __half* dst) {
    uint2 hv = make_uint2(pkh2(__float2half_rn(v.x), __float2half_rn(v.y)),
                          pkh2(__float2half_rn(v.z), __float2half_rn(v.w)));
    *reinterpret_cast<uint2*>(dst) = hv;
    return v.x * v.x + v.y * v.y + v.z * v.z + v.w * v.w;
}

// ===================== kernel 1: convert A = [x | h_prev] + silence mask =====================
__global__ void convert_A_kernel(const float* __restrict__ x, const float* __restrict__ h) {
    int m = blockIdx.x;
    int t = threadIdx.x;  // 256
    float4 vx = reinterpret_cast<const float4*>(x)[(size_t)m * 256 + t];
    float ss = h_store4(vx, g_A + (size_t)m * KDIM + 4 * t);
    float4 vh = reinterpret_cast<const float4*>(h)[(size_t)m * 256 + t];
    h_store4(vh, g_A + (size_t)m * KDIM + IDIM + 4 * t);

    __shared__ float red[256];
    red[t] = ss;
    __syncthreads();
    for (int s = 128; s > 0; s >>= 1) {
        if (t < s) red[t] += red[t + s];
        __syncthreads();
    }
    if (t == 0) g_mask[m] = (red[0] > 1e-6f) ? 1.0f : 0.0f;  // norm > 0.001
}

// ===================== kernel 2: convert packed weights (interleaved rows, fp16) ==========
__global__ void convert_W_kernel(const float* __restrict__ Wf, const float* __restrict__ Wi,
                                 const float* __restrict__ Wo, const float* __restrict__ Wc,
                                 const float* __restrict__ Vf, const float* __restrict__ Vi,
                                 const float* __restrict__ Vo, const float* __restrict__ Vc) {
    int n = blockIdx.x;     // 0..4095 (gate-major source index)
    int t = threadIdx.x;    // 256
    int g = n >> 10, j = n & 1023;
    int row = (j << 2) | g;  // interleaved destination row
    const float* W = (g == 0) ? Wf : (g == 1) ? Wi : (g == 2) ? Wo : Wc;
    const float* V = (g == 0) ? Vf : (g == 1) ? Vi : (g == 2) ? Vo : Vc;
    float4 vw = reinterpret_cast<const float4*>(W)[(size_t)j * 256 + t];
    h_store4(vw, g_W + (size_t)row * KDIM + 4 * t);
    float4 vv = reinterpret_cast<const float4*>(V)[(size_t)j * 256 + t];
    h_store4(vv, g_W + (size_t)row * KDIM + IDIM + 4 * t);
}

// ===================== kernel 3: combined bias (interleaved) =====================
__global__ void bias_kernel(const float* __restrict__ bWf, const float* __restrict__ bVf, const float* __restrict__ bf_,
                            const float* __restrict__ bWi, const float* __restrict__ bVi, const float* __restrict__ bi_,
                            const float* __restrict__ bWo, const float* __restrict__ bVo, const float* __restrict__ bo_,
                            const float* __restrict__ bWc, const float* __restrict__ bVc, const float* __restrict__ bc_) {
    int n = blockIdx.x * blockDim.x + threadIdx.x;
    if (n >= NDIM) return;
    int g = n >> 10, j = n & 1023;
    const float* a = (g == 0) ? bWf : (g == 1) ? bWi : (g == 2) ? bWo : bWc;
    const float* b = (g == 0) ? bVf : (g == 1) ? bVi : (g == 2) ? bVo : bVc;
    const float* c = (g == 0) ? bf_ : (g == 1) ? bi_ : (g == 2) ? bo_ : bc_;
    g_bias[(j << 2) | g] = a[j] + b[j] + c[j];
}

// ===================== kernel 4: pipelined GEMM + fused LSTM epilogue =====================
// gates = A*W^T  (fp16 inputs, fp32 accum), then activations -> out
// Round-8 config (256 thr, 4x2 warp grid, warp tile 32x64) + W-fragment
// double-buffering: the 4 W ldsm of k-step s+1 issue before the 16 MMAs of
// step s, so the tensor pipe only ever waits on the 2 A ldsm.
#define NTHREADS 256
#define BM 128
#define BN 128
#define BK 32
#define NK (KDIM / BK)          // 64 k-tiles
#define TOTAL_TILES 1024
#define GRID_CTAS 888           // persistent; 136 CTAs do 2 tiles
#define BUF_BYTES (128 * 64)    // 8192: 128 rows x 64B (pitch 64, swizzled)
#define STAGE_BYTES (2 * BUF_BYTES)    // 16384: A, W
#define NSTAGES 4
#define EPITCH 132              // floats per gates row in smem epilogue
#define GEMM_SMEM (128 * EPITCH * 4)   // 67584 >= NSTAGES*STAGE_BYTES (65536)

// swizzled byte offset of 16B chunk c (0..3) in row r, pitch 64.
// swz(r+16, c) == swz(r, c) + 1024 (swizzle term invariant under r += 16).
__device__ __forceinline__ uint32_t swz(int r, int c) {
    return (uint32_t)(r * 64 + ((c ^ ((r >> 1) & 3)) << 4));
}

// load this warp's 2 A fragments (32 rows) for one k16 step
__device__ __forceinline__ void load_afrags(uint32_t stage_base, uint32_t offA, uint32_t a[2][4]) {
    uint32_t aB = stage_base + offA;
    ldsm4(a[0], aB);
    ldsm4(a[1], aB + 1024u);
}

// load this warp's 4 W fragments (64 cols) for one k16 step
__device__ __forceinline__ void load_wfrags(uint32_t stage_base, uint32_t offW, uint32_t w[4][4]) {
    uint32_t wB = stage_base + offW;
    #pragma unroll
    for (int bt = 0; bt < 4; ++bt) ldsm4(w[bt], wB + (uint32_t)(bt * 1024));
}

// 16 independent MMAs on one fragment set (32x64 warp tile)
__device__ __forceinline__ void do_mma(float acc[2][8][4], uint32_t a[2][4], uint32_t w[4][4]) {
    #pragma unroll
    for (int am = 0; am < 2; ++am)
        #pragma unroll
        for (int bt = 0; bt < 4; ++bt) {
            mma16816(acc[am][2 * bt],     a[am], w[bt][0], w[bt][2]);
            mma16816(acc[am][2 * bt + 1], a[am], w[bt][1], w[bt][3]);
        }
}

__global__ void __launch_bounds__(NTHREADS, 2) gemm_kernel(const float* __restrict__ c_prev,
                                                           float* __restrict__ out, int n_out) {
    extern __shared__ char smem[];
    uint32_t sb = smem_to_u32(smem);
    int tid = threadIdx.x, wid = tid >> 5, lid = tid & 31;
    int wm = (wid >> 1) * 32;   // 4x2 warp grid, warp tile 32x64
    int wn = (wid & 1) * 64;
    int lrow = lid & 15;
    int cbase = lid >> 4;       // 0 or 1: second 16B chunk within k16-step

    // ---- thread-invariant ldmatrix base offsets, one per k16-step (2 per BK=32)
    uint32_t offA0[2], offW0[2];
    #pragma unroll
    for (int ks = 0; ks < 2; ++ks) {
        int cidx = ks * 2 + cbase;
        offA0[ks] = swz(wm + lrow, cidx);                       // A buffer at 0
        offW0[ks] = swz(wn + lrow, cidx) + (uint32_t)BUF_BYTES; // W buffer at +BUF
    }

    // ---- thread-invariant cp.async producer offsets (256 threads x 2 chunks = 128 rows x 4)
    uint32_t ls_soff[2], ls_goff[2];
    #pragma unroll
    for (int i = 0; i < 2; ++i) {
        int q = tid + i * NTHREADS;
        int r = q >> 2, c = q & 3;
        ls_soff[i] = swz(r, c);
        ls_goff[i] = (uint32_t)(r * KDIM + c * 8);
    }

    for (int t = blockIdx.x; t < TOTAL_TILES; t += GRID_CTAS) {
        int m0 = (t >> 5) * BM;
        int n0 = (t & 31) * BN;
        int j_base = n0 >> 2;   // interleaved: 32 j's per CTA tile

        const __half* pA = g_A + (size_t)m0 * KDIM;
        const __half* pW = g_W + (size_t)n0 * KDIM;

        #define LOAD_STAGE(stage, kt) do {                                      \
            uint32_t s0_ = sb + (uint32_t)(stage) * STAGE_BYTES;                \
            uint32_t k0_ = (uint32_t)((kt) * BK);                               \
            cp16(s0_ + ls_soff[0],             pA + k0_ + ls_goff[0]);          \
            cp16(s0_ + ls_soff[1],             pA + k0_ + ls_goff[1]);          \
            cp16(s0_ + BUF_BYTES + ls_soff[0], pW + k0_ + ls_goff[0]);          \
            cp16(s0_ + BUF_BYTES + ls_soff[1], pW + k0_ + ls_goff[1]);          \
            CP_COMMIT();                                                        \
        } while (0)

        float acc[2][8][4];
        #pragma unroll
        for (int i = 0; i < 2; ++i)
            #pragma unroll
            for (int j = 0; j < 8; ++j)
                #pragma unroll
                for (int k = 0; k < 4; ++k) acc[i][j][k] = 0.0f;

        // prologue: stages 0,1,2 in flight; stages 0,1 complete+visible
        LOAD_STAGE(0, 0);
        LOAD_STAGE(1, 1);
        LOAD_STAGE(2, 2);
        CP_WAIT(1);
        __syncthreads();

        uint32_t a[2][4];        // single-buffered A fragments (2 ldsm)
        uint32_t w[2][4][4];     // double-buffered W fragments (4 ldsm each)
        load_wfrags(sb, offW0[0], w[0]);   // preload W(kt0, ks0)

        #pragma unroll 1
        for (int kt = 0; kt < NK; ++kt) {
            uint32_t cur = sb + (uint32_t)(kt & (NSTAGES - 1)) * STAGE_BYTES;
            uint32_t nxt = sb + (uint32_t)((kt + 1) & (NSTAGES - 1)) * STAGE_BYTES;

            // ks = 0: A(cur,ks0) + prefetch W(cur,ks1), mma on resident w[0]
            load_afrags(cur, offA0[0], a);
            load_wfrags(cur, offW0[1], w[1]);
            do_mma(acc, a, w[0]);

            // ks = 1: A(cur,ks1) + prefetch W(kt+1,ks0) (stage kt+1 is visible:
            // the end-of-previous-iter CP_WAIT(1)+sync guaranteed it), mma on w[1]
            load_afrags(cur, offA0[1], a);
            if (kt + 1 < NK)
                load_wfrags(nxt, offW0[0], w[0]);
            do_mma(acc, a, w[1]);

            // prefetch tile kt+3 (overwrites stage (kt-1)%4: last ldsm-read of it
            // was before the previous barrier, so the write is ordered-safe)
            if (kt + 3 < NK)
                LOAD_STAGE((kt + 3) & (NSTAGES - 1), kt + 3);
            if (kt + 1 < NK) {
                CP_WAIT(1);       // stages <= kt+2 complete
                __syncthreads();  // ... and CTA-visible
            }
        }
        #undef LOAD_STAGE

        // ===== fused epilogue: acc -> smem -> activations -> out =====
        __syncthreads();   // all warps done with stage buffers; reuse smem for gates
        float* sg = reinterpret_cast<float*>(smem);   // [128][EPITCH]
        int gid = lid >> 2, tig = lid & 3;
        #pragma unroll
        for (int am = 0; am < 2; ++am) {
            #pragma unroll
            for (int bn = 0; bn < 8; ++bn) {
                const float* c = acc[am][bn];
                int row = wm + am * 16 + gid;
                int col = wn + bn * 8 + tig * 2;
                sg[row * EPITCH + col]           = c[0];
                sg[row * EPITCH + col + 1]       = c[1];
                sg[(row + 8) * EPITCH + col]     = c[2];
                sg[(row + 8) * EPITCH + col + 1] = c[3];
            }
        }
        __syncthreads();

        const int BH = BDIM * HDIM;
        #pragma unroll
        for (int i = 0; i < 16; ++i) {
            int idx = tid + i * NTHREADS;   // 128 rows x 32 j
            int row = idx >> 5, lj = idx & 31;
            float4 gv = *reinterpret_cast<const float4*>(&sg[row * EPITCH + lj * 4]);
            int jg = j_base + lj;
            float4 bv = *reinterpret_cast<const float4*>(&g_bias[jg * 4]);
            float fp = gv.x + bv.x, ip = gv.y + bv.y, op = gv.z + bv.z, cp = gv.w + bv.w;
            float ft = 1.0f / (1.0f + expf(-fp));
            float it = 1.0f / (1.0f + expf(-ip));
            float ot = 1.0f / (1.0f + expf(-op));
            float ct = tanhf(cp);
            int m = m0 + row;
            int oidx = m * HDIM + jg;
            float cpv = c_prev[oidx];
            float cn = ft * cpv + it * cpv + g_mask[m] * (it * ct);
            float hn = ot * tanhf(cn);
            out[oidx] = hn;
            if (BH + oidx < n_out)     out[BH + oidx] = cn;
            if (2 * BH + oidx < n_out) out[2 * BH + oidx] = ct;
        }
        __syncthreads();   // epilogue reads done before next tile's cp.async writes
    }
}

// ===================== launcher =====================
extern "C" void kernel_launch(void* const* d_in, const int* in_sizes, int n_in,
                              void* d_out, int out_size) {
    (void)n_in;
    const float* x      = (const float*)d_in[0];
    const float* h_prev = (const float*)d_in[1];
    const float* c_prev = (const float*)d_in[2];
    // d_in[3] = c_prev_tilde_dummy (unused)

    // Input order detection (dict order vs signature order); see round-2 notes.
    const float *W[4], *V[4], *bW[4], *bV[4], *bx[4];
    if (in_sizes[8] > 100000) {
        for (int g = 0; g < 4; ++g) {   // dict order
            W[g]  = (const float*)d_in[4 + 4 * g];
            bW[g] = (const float*)d_in[5 + 4 * g];
            V[g]  = (const float*)d_in[6 + 4 * g];
            bV[g] = (const float*)d_in[7 + 4 * g];
            bx[g] = (const float*)d_in[20 + g];
        }
    } else {
        for (int g = 0; g < 4; ++g) {   // signature order
            W[g]  = (const float*)d_in[4 + 5 * g];
            bW[g] = (const float*)d_in[5 + 5 * g];
            V[g]  = (const float*)d_in[6 + 5 * g];
            bV[g] = (const float*)d_in[7 + 5 * g];
            bx[g] = (const float*)d_in[8 + 5 * g];
        }
    }

    convert_A_kernel<<<BDIM, 256>>>(x, h_prev);
    convert_W_kernel<<<NDIM, 256>>>(W[0], W[1], W[2], W[3], V[0], V[1], V[2], V[3]);
    bias_kernel<<<NDIM / 256, 256>>>(bW[0], bV[0], bx[0], bW[1], bV[1], bx[1],
                                     bW[2], bV[2], bx[2], bW[3], bV[3], bx[3]);

    cudaFuncSetAttribute(gemm_kernel, cudaFuncAttributeMaxDynamicSharedMemorySize,
                         (int)GEMM_SMEM);
    gemm_kernel<<<GRID_CTAS, NTHREADS, GEMM_SMEM>>>(c_prev, (float*)d_out, out_size);
}

// round 14
// speedup vs baseline: 1.1536x; 1.0240x over previous
#include <cuda_runtime.h>
#include <cuda_fp16.h>
#include <cstdint>

// ===================== problem dims =====================
#define BDIM 4096
#define IDIM 1024
#define HDIM 1024
#define KDIM 2048   // I + H
#define NDIM 4096   // 4 * H, INTERLEAVED: n = j*4 + g  (g in {f,i,o,c})

// ===================== device scratch (static, allowed) =====================
__device__ __align__(256) __half g_A[(size_t)BDIM * KDIM];    // fp16(x|h)
__device__ __align__(256) __half g_W[(size_t)NDIM * KDIM];    // fp16(W), interleaved rows
__device__ __align__(256) float  g_bias[NDIM];                // interleaved j*4+g
__device__ __align__(256) float  g_mask[BDIM];

// ===================== small PTX helpers (sm_80+ features only) =====================
__device__ __forceinline__ uint32_t smem_to_u32(const void* p) {
    uint32_t a;
    asm("{ .reg .u64 t; cvta.to.shared.u64 t, %1; cvt.u32.u64 %0, t; }" : "=r"(a) : "l"(p));
    return a;
}

__device__ __forceinline__ void cp16(uint32_t saddr, const void* g) {
    asm volatile("cp.async.cg.shared.global [%0], [%1], 16;" :: "r"(saddr), "l"(g) : "memory");
}

#define CP_COMMIT() asm volatile("cp.async.commit_group;" ::: "memory")
#define CP_WAIT(N)  asm volatile("cp.async.wait_group %0;" :: "n"(N) : "memory")

__device__ __forceinline__ void ldsm4(uint32_t* r, uint32_t addr) {
    asm volatile("ldmatrix.sync.aligned.m8n8.x4.shared.b16 {%0,%1,%2,%3}, [%4];"
                 : "=r"(r[0]), "=r"(r[1]), "=r"(r[2]), "=r"(r[3]) : "r"(addr));
}

__device__ __forceinline__ void mma16816(float* c, const uint32_t* a, uint32_t b0, uint32_t b1) {
    asm volatile(
        "mma.sync.aligned.m16n8k16.row.col.f32.f16.f16.f32 "
        "{%0,%1,%2,%3}, {%4,%5,%6,%7}, {%8,%9}, {%0,%1,%2,%3};"
        : "+f"(c[0]), "+f"(c[1]), "+f"(c[2]), "+f"(c[3])
        : "r"(a[0]), "r"(a[1]), "r"(a[2]), "r"(a[3]), "r"(b0), "r"(b1));
}

// ===================== conversion helpers =====================
__device__ __forceinline__ uint32_t pkh2(__half a, __half b) {
    __half2 t = __halves2half2(a, b);
    return *reinterpret_cast<uint32_t*>(&t);
}

// store 4 fp16 and return sum of squares
__device__ __forceinline__ float h_store4(float4 v, __half* dst) {
    uint2 hv = make_uint2(pkh2(__float2half_rn(v.x), __float2half_rn(v.y)),
                          pkh2(__float2half_rn(v.z), __float2half_rn(v.w)));
    *reinterpret_cast<uint2*>(dst) = hv;
    return v.x * v.x + v.y * v.y + v.z * v.z + v.w * v.w;
}

// ===================== kernel 1: merged converts (A + silence mask, W) ==========
// blocks [0, BDIM): A rows; blocks [BDIM, BDIM+NDIM): W rows (interleaved dest)
__global__ void convert_AW_kernel(const float* __restrict__ x, const float* __restrict__ h,
                                  const float* __restrict__ Wf, const float* __restrict__ Wi,
                                  const float* __restrict__ Wo, const float* __restrict__ Wc,
                                  const float* __restrict__ Vf, const float* __restrict__ Vi,
                                  const float* __restrict__ Vo, const float* __restrict__ Vc) {
    int b = blockIdx.x;
    int t = threadIdx.x;  // 256
    if (b < BDIM) {
        int m = b;
        float4 vx = reinterpret_cast<const float4*>(x)[(size_t)m * 256 + t];
        float ss = h_store4(vx, g_A + (size_t)m * KDIM + 4 * t);
        float4 vh = reinterpret_cast<const float4*>(h)[(size_t)m * 256 + t];
        h_store4(vh, g_A + (size_t)m * KDIM + IDIM + 4 * t);

        __shared__ float red[256];
        red[t] = ss;
        __syncthreads();
        for (int s = 128; s > 0; s >>= 1) {
            if (t < s) red[t] += red[t + s];
            __syncthreads();
        }
        if (t == 0) g_mask[m] = (red[0] > 1e-6f) ? 1.0f : 0.0f;  // norm > 0.001
    } else {
        int n = b - BDIM;        // 0..4095 (gate-major source index)
        int g = n >> 10, j = n & 1023;
        int row = (j << 2) | g;  // interleaved destination row
        const float* W = (g == 0) ? Wf : (g == 1) ? Wi : (g == 2) ? Wo : Wc;
        const float* V = (g == 0) ? Vf : (g == 1) ? Vi : (g == 2) ? Vo : Vc;
        float4 vw = reinterpret_cast<const float4*>(W)[(size_t)j * 256 + t];
        h_store4(vw, g_W + (size_t)row * KDIM + 4 * t);
        float4 vv = reinterpret_cast<const float4*>(V)[(size_t)j * 256 + t];
        h_store4(vv, g_W + (size_t)row * KDIM + IDIM + 4 * t);
    }
}

// ===================== kernel 2: combined bias (interleaved) =====================
__global__ void bias_kernel(const float* __restrict__ bWf, const float* __restrict__ bVf, const float* __restrict__ bf_,
                            const float* __restrict__ bWi, const float* __restrict__ bVi, const float* __restrict__ bi_,
                            const float* __restrict__ bWo, const float* __restrict__ bVo, const float* __restrict__ bo_,
                            const float* __restrict__ bWc, const float* __restrict__ bVc, const float* __restrict__ bc_) {
    int n = blockIdx.x * blockDim.x + threadIdx.x;
    if (n >= NDIM) return;
    int g = n >> 10, j = n & 1023;
    const float* a = (g == 0) ? bWf : (g == 1) ? bWi : (g == 2) ? bWo : bWc;
    const float* b = (g == 0) ? bVf : (g == 1) ? bVi : (g == 2) ? bVo : bVc;
    const float* c = (g == 0) ? bf_ : (g == 1) ? bi_ : (g == 2) ? bo_ : bc_;
    g_bias[(j << 2) | g] = a[j] + b[j] + c[j];
}

// ===================== kernel 3: pipelined GEMM + fused LSTM epilogue =====================
// gates = A*W^T  (fp16 inputs, fp32 accum), then activations -> out
// Proven round-8 structure: 256 thr, 4x2 warp grid, warp tile 32x64,
// top-of-loop tapered waits, single-buffered fragments. NSTAGES 4 -> 5.
#define NTHREADS 256
#define BM 128
#define BN 128
#define BK 32
#define NK (KDIM / BK)          // 64 k-tiles
#define TOTAL_TILES 1024
#define GRID_CTAS 888           // persistent; 136 CTAs do 2 tiles
#define BUF_BYTES (128 * 64)    // 8192: 128 rows x 64B (pitch 64, swizzled)
#define STAGE_BYTES (2 * BUF_BYTES)    // 16384: A, W
#define NSTAGES 5
#define EPITCH 132              // floats per gates row in smem epilogue
#define GEMM_SMEM (NSTAGES * STAGE_BYTES)   // 81920 >= 128*EPITCH*4 (67584)

// swizzled byte offset of 16B chunk c (0..3) in row r, pitch 64.
// swz(r+16, c) == swz(r, c) + 1024 (swizzle term invariant under r += 16).
__device__ __forceinline__ uint32_t swz(int r, int c) {
    return (uint32_t)(r * 64 + ((c ^ ((r >> 1) & 3)) << 4));
}

__global__ void __launch_bounds__(NTHREADS, 2) gemm_kernel(const float* __restrict__ c_prev,
                                                           float* __restrict__ out, int n_out) {
    extern __shared__ char smem[];
    uint32_t sb = smem_to_u32(smem);
    int tid = threadIdx.x, wid = tid >> 5, lid = tid & 31;
    int wm = (wid >> 1) * 32;   // 4x2 warp grid, warp tile 32x64
    int wn = (wid & 1) * 64;
    int lrow = lid & 15;
    int cbase = lid >> 4;       // 0 or 1: second 16B chunk within k16-step

    // ---- thread-invariant ldmatrix base offsets, one per k16-step (2 per BK=32)
    uint32_t offA0[2], offW0[2];
    #pragma unroll
    for (int ks = 0; ks < 2; ++ks) {
        int cidx = ks * 2 + cbase;
        offA0[ks] = swz(wm + lrow, cidx);                       // A buffer at 0
        offW0[ks] = swz(wn + lrow, cidx) + (uint32_t)BUF_BYTES; // W buffer at +BUF
    }

    // ---- thread-invariant cp.async producer offsets (256 threads x 2 chunks = 128 rows x 4)
    uint32_t ls_soff[2], ls_goff[2];
    #pragma unroll
    for (int i = 0; i < 2; ++i) {
        int q = tid + i * NTHREADS;
        int r = q >> 2, c = q & 3;
        ls_soff[i] = swz(r, c);
        ls_goff[i] = (uint32_t)(r * KDIM + c * 8);
    }

    for (int t = blockIdx.x; t < TOTAL_TILES; t += GRID_CTAS) {
        int m0 = (t >> 5) * BM;
        int n0 = (t & 31) * BN;
        int j_base = n0 >> 2;   // interleaved: 32 j's per CTA tile

        const __half* pA = g_A + (size_t)m0 * KDIM;
        const __half* pW = g_W + (size_t)n0 * KDIM;

        #define LOAD_STAGE(stage, kt) do {                                      \
            uint32_t s0_ = sb + (uint32_t)(stage) * STAGE_BYTES;                \
            uint32_t k0_ = (uint32_t)((kt) * BK);                               \
            cp16(s0_ + ls_soff[0],             pA + k0_ + ls_goff[0]);          \
            cp16(s0_ + ls_soff[1],             pA + k0_ + ls_goff[1]);          \
            cp16(s0_ + BUF_BYTES + ls_soff[0], pW + k0_ + ls_goff[0]);          \
            cp16(s0_ + BUF_BYTES + ls_soff[1], pW + k0_ + ls_goff[1]);          \
            CP_COMMIT();                                                        \
        } while (0)

        float acc[2][8][4];
        #pragma unroll
        for (int i = 0; i < 2; ++i)
            #pragma unroll
            for (int j = 0; j < 8; ++j)
                #pragma unroll
                for (int k = 0; k < 4; ++k) acc[i][j][k] = 0.0f;

        // prologue: stages 0..3 in flight (prefetch distance 4)
        LOAD_STAGE(0, 0);
        LOAD_STAGE(1, 1);
        LOAD_STAGE(2, 2);
        LOAD_STAGE(3, 3);

        int st_cur = 0;         // stage of tile kt
        int st_pre = 4;         // stage for tile kt+4
        #pragma unroll 1
        for (int kt = 0; kt < NK; ++kt) {
            // top-of-loop tapered wait: tile kt must be complete.
            // allowed pending = number of commits for tiles > kt = min(4, NK-1-kt) - 1 adjusted;
            // with commits stopping at kt=NK-5, pending ceiling is min(3, NK-1-kt).
            int rem = NK - 1 - kt;
            if (rem >= 3)      { CP_WAIT(3); }
            else if (rem == 2) { CP_WAIT(2); }
            else if (rem == 1) { CP_WAIT(1); }
            else               { CP_WAIT(0); }
            __syncthreads();   // tile kt visible to all; frees stage st_pre for writes

            uint32_t cur = sb + (uint32_t)st_cur * STAGE_BYTES;

            #pragma unroll
            for (int ks = 0; ks < 2; ++ks) {
                uint32_t aB = cur + offA0[ks];   // A fragment base
                uint32_t wB = cur + offW0[ks];   // W fragment base

                uint32_t a[2][4], w0[4][4];
                ldsm4(a[0], aB);
                ldsm4(a[1], aB + 1024u);
                #pragma unroll
                for (int bn = 0; bn < 4; ++bn)
                    ldsm4(w0[bn], wB + (uint32_t)(bn * 1024));

                #pragma unroll
                for (int am = 0; am < 2; ++am)
                    #pragma unroll
                    for (int bn = 0; bn < 4; ++bn) {
                        mma16816(acc[am][2 * bn],     a[am], w0[bn][0], w0[bn][2]);
                        mma16816(acc[am][2 * bn + 1], a[am], w0[bn][1], w0[bn][3]);
                    }
            }

            // prefetch tile kt+4 (top barrier of next iter orders the WAR)
            if (kt + 4 < NK)
                LOAD_STAGE(st_pre, kt + 4);
            st_cur = (st_cur + 1 == NSTAGES) ? 0 : st_cur + 1;
            st_pre = (st_pre + 1 == NSTAGES) ? 0 : st_pre + 1;
        }
        #undef LOAD_STAGE

        // ===== fused epilogue: acc -> smem -> activations -> out =====
        __syncthreads();   // done reading stage buffers; reuse smem for gates
        float* sg = reinterpret_cast<float*>(smem);   // [128][EPITCH]
        int gid = lid >> 2, tig = lid & 3;
        #pragma unroll
        for (int am = 0; am < 2; ++am) {
            #pragma unroll
            for (int bn = 0; bn < 8; ++bn) {
                const float* c = acc[am][bn];
                int row = wm + am * 16 + gid;
                int col = wn + bn * 8 + tig * 2;
                sg[row * EPITCH + col]           = c[0];
                sg[row * EPITCH + col + 1]       = c[1];
                sg[(row + 8) * EPITCH + col]     = c[2];
                sg[(row + 8) * EPITCH + col + 1] = c[3];
            }
        }
        __syncthreads();

        const int BH = BDIM * HDIM;
        #pragma unroll
        for (int i = 0; i < 16; ++i) {
            int idx = tid + i * NTHREADS;   // 128 rows x 32 j
            int row = idx >> 5, lj = idx & 31;
            float4 gv = *reinterpret_cast<const float4*>(&sg[row * EPITCH + lj * 4]);
            int jg = j_base + lj;
            float4 bv = *reinterpret_cast<const float4*>(&g_bias[jg * 4]);
            float fp = gv.x + bv.x, ip = gv.y + bv.y, op = gv.z + bv.z, cp = gv.w + bv.w;
            float ft = 1.0f / (1.0f + expf(-fp));
            float it = 1.0f / (1.0f + expf(-ip));
            float ot = 1.0f / (1.0f + expf(-op));
            float ct = tanhf(cp);
            int m = m0 + row;
            int oidx = m * HDIM + jg;
            float cpv = c_prev[oidx];
            float cn = ft * cpv + it * cpv + g_mask[m] * (it * ct);
            float hn = ot * tanhf(cn);
            out[oidx] = hn;
            if (BH + oidx < n_out)     out[BH + oidx] = cn;
            if (2 * BH + oidx < n_out) out[2 * BH + oidx] = ct;
        }
        __syncthreads();   // epilogue reads done before next tile's cp.async writes
    }
}

// ===================== launcher =====================
extern "C" void kernel_launch(void* const* d_in, const int* in_sizes, int n_in,
                              void* d_out, int out_size) {
    (void)n_in;
    const float* x      = (const float*)d_in[0];
    const float* h_prev = (const float*)d_in[1];
    const float* c_prev = (const float*)d_in[2];
    // d_in[3] = c_prev_tilde_dummy (unused)

    // Input order detection (dict order vs signature order); see round-2 notes.
    const float *W[4], *V[4], *bW[4], *bV[4], *bx[4];
    if (in_sizes[8] > 100000) {
        for (int g = 0; g < 4; ++g) {   // dict order
            W[g]  = (const float*)d_in[4 + 4 * g];
            bW[g] = (const float*)d_in[5 + 4 * g];
            V[g]  = (const float*)d_in[6 + 4 * g];
            bV[g] = (const float*)d_in[7 + 4 * g];
            bx[g] = (const float*)d_in[20 + g];
        }
    } else {
        for (int g = 0; g < 4; ++g) {   // signature order
            W[g]  = (const float*)d_in[4 + 5 * g];
            bW[g] = (const float*)d_in[5 + 5 * g];
            V[g]  = (const float*)d_in[6 + 5 * g];
            bV[g] = (const float*)d_in[7 + 5 * g];
            bx[g] = (const float*)d_in[8 + 5 * g];
        }
    }

    convert_AW_kernel<<<BDIM + NDIM, 256>>>(x, h_prev,
                                            W[0], W[1], W[2], W[3],
                                            V[0], V[1], V[2], V[3]);
    bias_kernel<<<NDIM / 256, 256>>>(bW[0], bV[0], bx[0], bW[1], bV[1], bx[1],
                                     bW[2], bV[2], bx[2], bW[3], bV[3], bx[3]);

    cudaFuncSetAttribute(gemm_kernel, cudaFuncAttributeMaxDynamicSharedMemorySize,
                         (int)GEMM_SMEM);
    gemm_kernel<<<GRID_CTAS, NTHREADS, GEMM_SMEM>>>(c_prev, (float*)d_out, out_size);
}

// round 15
// speedup vs baseline: 1.2537x; 1.0867x over previous
#include <cuda_runtime.h>
#include <cuda_fp16.h>
#include <cstdint>

// ===================== problem dims =====================
#define BDIM 4096
#define IDIM 1024
#define HDIM 1024
#define KDIM 2048   // I + H
#define NDIM 4096   // 4 * H, INTERLEAVED: n = j*4 + g  (g in {f,i,o,c})

// ===================== device scratch (static, allowed) =====================
__device__ __align__(256) __half g_A[(size_t)BDIM * KDIM];    // fp16(x|h)
__device__ __align__(256) __half g_W[(size_t)NDIM * KDIM];    // fp16(W), interleaved rows
__device__ __align__(256) float  g_bias[NDIM];                // interleaved j*4+g
__device__ __align__(256) float  g_mask[BDIM];

// ===================== small PTX helpers (sm_80+ features only) =====================
__device__ __forceinline__ uint32_t smem_to_u32(const void* p) {
    uint32_t a;
    asm("{ .reg .u64 t; cvta.to.shared.u64 t, %1; cvt.u32.u64 %0, t; }" : "=r"(a) : "l"(p));
    return a;
}

__device__ __forceinline__ void cp16(uint32_t saddr, const void* g) {
    asm volatile("cp.async.cg.shared.global [%0], [%1], 16;" :: "r"(saddr), "l"(g) : "memory");
}

#define CP_COMMIT() asm volatile("cp.async.commit_group;" ::: "memory")
#define CP_WAIT(N)  asm volatile("cp.async.wait_group %0;" :: "n"(N) : "memory")

__device__ __forceinline__ void ldsm4(uint32_t* r, uint32_t addr) {
    asm volatile("ldmatrix.sync.aligned.m8n8.x4.shared.b16 {%0,%1,%2,%3}, [%4];"
                 : "=r"(r[0]), "=r"(r[1]), "=r"(r[2]), "=r"(r[3]) : "r"(addr));
}

__device__ __forceinline__ void mma16816(float* c, const uint32_t* a, uint32_t b0, uint32_t b1) {
    asm volatile(
        "mma.sync.aligned.m16n8k16.row.col.f32.f16.f16.f32 "
        "{%0,%1,%2,%3}, {%4,%5,%6,%7}, {%8,%9}, {%0,%1,%2,%3};"
        : "+f"(c[0]), "+f"(c[1]), "+f"(c[2]), "+f"(c[3])
        : "r"(a[0]), "r"(a[1]), "r"(a[2]), "r"(a[3]), "r"(b0), "r"(b1));
}

// ===================== conversion helpers =====================
__device__ __forceinline__ uint32_t pkh2(__half a, __half b) {
    __half2 t = __halves2half2(a, b);
    return *reinterpret_cast<uint32_t*>(&t);
}

// store 4 fp16 and return sum of squares
__device__ __forceinline__ float h_store4(float4 v, __half* dst) {
    uint2 hv = make_uint2(pkh2(__float2half_rn(v.x), __float2half_rn(v.y)),
                          pkh2(__float2half_rn(v.z), __float2half_rn(v.w)));
    *reinterpret_cast<uint2*>(dst) = hv;
    return v.x * v.x + v.y * v.y + v.z * v.z + v.w * v.w;
}

// ===================== kernel 1: merged prep (A + mask, W, bias) ==========
// blocks [0, BDIM): A rows
// blocks [BDIM, BDIM+NDIM): W rows (gate-major source -> interleaved dest)
// blocks [BDIM+NDIM, BDIM+NDIM+16): bias (16 blocks x 256 = 4096)
__global__ void prep_kernel(const float* __restrict__ x, const float* __restrict__ h,
                            const float* __restrict__ Wf, const float* __restrict__ Wi,
                            const float* __restrict__ Wo, const float* __restrict__ Wc,
                            const float* __restrict__ Vf, const float* __restrict__ Vi,
                            const float* __restrict__ Vo, const float* __restrict__ Vc,
                            const float* __restrict__ bWf, const float* __restrict__ bVf, const float* __restrict__ bf_,
                            const float* __restrict__ bWi, const float* __restrict__ bVi, const float* __restrict__ bi_,
                            const float* __restrict__ bWo, const float* __restrict__ bVo, const float* __restrict__ bo_,
                            const float* __restrict__ bWc, const float* __restrict__ bVc, const float* __restrict__ bc_) {
    int b = blockIdx.x;
    int t = threadIdx.x;  // 256
    if (b < BDIM) {
        int m = b;
        float4 vx = reinterpret_cast<const float4*>(x)[(size_t)m * 256 + t];
        float ss = h_store4(vx, g_A + (size_t)m * KDIM + 4 * t);
        float4 vh = reinterpret_cast<const float4*>(h)[(size_t)m * 256 + t];
        h_store4(vh, g_A + (size_t)m * KDIM + IDIM + 4 * t);

        __shared__ float red[256];
        red[t] = ss;
        __syncthreads();
        for (int s = 128; s > 0; s >>= 1) {
            if (t < s) red[t] += red[t + s];
            __syncthreads();
        }
        if (t == 0) g_mask[m] = (red[0] > 1e-6f) ? 1.0f : 0.0f;  // norm > 0.001
    } else if (b < BDIM + NDIM) {
        int n = b - BDIM;        // 0..4095 (gate-major source index)
        int g = n >> 10, j = n & 1023;
        int row = (j << 2) | g;  // interleaved destination row
        const float* W = (g == 0) ? Wf : (g == 1) ? Wi : (g == 2) ? Wo : Wc;
        const float* V = (g == 0) ? Vf : (g == 1) ? Vi : (g == 2) ? Vo : Vc;
        float4 vw = reinterpret_cast<const float4*>(W)[(size_t)j * 256 + t];
        h_store4(vw, g_W + (size_t)row * KDIM + 4 * t);
        float4 vv = reinterpret_cast<const float4*>(V)[(size_t)j * 256 + t];
        h_store4(vv, g_W + (size_t)row * KDIM + IDIM + 4 * t);
    } else {
        int n = (b - BDIM - NDIM) * 256 + t;   // 0..4095
        int g = n >> 10, j = n & 1023;
        const float* a = (g == 0) ? bWf : (g == 1) ? bWi : (g == 2) ? bWo : bWc;
        const float* bb = (g == 0) ? bVf : (g == 1) ? bVi : (g == 2) ? bVo : bVc;
        const float* c = (g == 0) ? bf_ : (g == 1) ? bi_ : (g == 2) ? bo_ : bc_;
        g_bias[(j << 2) | g] = a[j] + bb[j] + c[j];
    }
}

// ===================== kernel 2: pipelined GEMM + fused LSTM epilogue =====================
// gates = A*W^T  (fp16 inputs, fp32 accum), then activations -> out
// Proven round-8 structure: 256 thr, 4x2 warp grid, warp tile 32x64,
// 4 stages, top-of-loop waits. Hot loop branch-free (tail iterations peeled).
#define NTHREADS 256
#define BM 128
#define BN 128
#define BK 32
#define NK (KDIM / BK)          // 64 k-tiles
#define TOTAL_TILES 1024
#define GRID_CTAS 888           // persistent; 136 CTAs do 2 tiles
#define BUF_BYTES (128 * 64)    // 8192: 128 rows x 64B (pitch 64, swizzled)
#define STAGE_BYTES (2 * BUF_BYTES)    // 16384: A, W
#define NSTAGES 4
#define EPITCH 132              // floats per gates row in smem epilogue
#define GEMM_SMEM (128 * EPITCH * 4)   // 67584 >= NSTAGES*STAGE_BYTES (65536)

// swizzled byte offset of 16B chunk c (0..3) in row r, pitch 64.
// swz(r+16, c) == swz(r, c) + 1024 (swizzle term invariant under r += 16).
__device__ __forceinline__ uint32_t swz(int r, int c) {
    return (uint32_t)(r * 64 + ((c ^ ((r >> 1) & 3)) << 4));
}

__global__ void __launch_bounds__(NTHREADS, 2) gemm_kernel(const float* __restrict__ c_prev,
                                                           float* __restrict__ out, int n_out) {
    extern __shared__ char smem[];
    uint32_t sb = smem_to_u32(smem);
    int tid = threadIdx.x, wid = tid >> 5, lid = tid & 31;
    int wm = (wid >> 1) * 32;   // 4x2 warp grid, warp tile 32x64
    int wn = (wid & 1) * 64;
    int lrow = lid & 15;
    int cbase = lid >> 4;       // 0 or 1: second 16B chunk within k16-step

    // ---- thread-invariant ldmatrix base offsets, one per k16-step (2 per BK=32)
    uint32_t offA0[2], offW0[2];
    #pragma unroll
    for (int ks = 0; ks < 2; ++ks) {
        int cidx = ks * 2 + cbase;
        offA0[ks] = swz(wm + lrow, cidx);                       // A buffer at 0
        offW0[ks] = swz(wn + lrow, cidx) + (uint32_t)BUF_BYTES; // W buffer at +BUF
    }

    // ---- thread-invariant cp.async producer offsets (256 threads x 2 chunks = 128 rows x 4)
    uint32_t ls_soff[2], ls_goff[2];
    #pragma unroll
    for (int i = 0; i < 2; ++i) {
        int q = tid + i * NTHREADS;
        int r = q >> 2, c = q & 3;
        ls_soff[i] = swz(r, c);
        ls_goff[i] = (uint32_t)(r * KDIM + c * 8);
    }

    for (int t = blockIdx.x; t < TOTAL_TILES; t += GRID_CTAS) {
        int m0 = (t >> 5) * BM;
        int n0 = (t & 31) * BN;
        int j_base = n0 >> 2;   // interleaved: 32 j's per CTA tile

        const __half* pA = g_A + (size_t)m0 * KDIM;
        const __half* pW = g_W + (size_t)n0 * KDIM;

        #define LOAD_STAGE(stage, kt) do {                                      \
            uint32_t s0_ = sb + (uint32_t)(stage) * STAGE_BYTES;                \
            uint32_t k0_ = (uint32_t)((kt) * BK);                               \
            cp16(s0_ + ls_soff[0],             pA + k0_ + ls_goff[0]);          \
            cp16(s0_ + ls_soff[1],             pA + k0_ + ls_goff[1]);          \
            cp16(s0_ + BUF_BYTES + ls_soff[0], pW + k0_ + ls_goff[0]);          \
            cp16(s0_ + BUF_BYTES + ls_soff[1], pW + k0_ + ls_goff[1]);          \
            CP_COMMIT();                                                        \
        } while (0)

        float acc[2][8][4];
        #pragma unroll
        for (int i = 0; i < 2; ++i)
            #pragma unroll
            for (int j = 0; j < 8; ++j)
                #pragma unroll
                for (int k = 0; k < 4; ++k) acc[i][j][k] = 0.0f;

        // one k16-step pair on stage buffer at 'cur'
        #define COMPUTE_TILE(cur_) do {                                           \
            uint32_t cur = (cur_);                                                \
            _Pragma("unroll")                                                     \
            for (int ks = 0; ks < 2; ++ks) {                                      \
                uint32_t aB = cur + offA0[ks];                                    \
                uint32_t wB = cur + offW0[ks];                                    \
                uint32_t a[2][4], w0[4][4];                                       \
                ldsm4(a[0], aB);                                                  \
                ldsm4(a[1], aB + 1024u);                                          \
                _Pragma("unroll")                                                 \
                for (int bn = 0; bn < 4; ++bn)                                    \
                    ldsm4(w0[bn], wB + (uint32_t)(bn * 1024));                    \
                _Pragma("unroll")                                                 \
                for (int am = 0; am < 2; ++am)                                    \
                    _Pragma("unroll")                                             \
                    for (int bn = 0; bn < 4; ++bn) {                              \
                        mma16816(acc[am][2 * bn],     a[am], w0[bn][0], w0[bn][2]); \
                        mma16816(acc[am][2 * bn + 1], a[am], w0[bn][1], w0[bn][3]); \
                    }                                                             \
            }                                                                     \
        } while (0)

        // prologue: stages 0,1,2 (prefetch distance 3)
        LOAD_STAGE(0, 0);
        LOAD_STAGE(1, 1);
        LOAD_STAGE(2, 2);

        // hot loop: branch-free (loads always issued; waits constant)
        #pragma unroll 1
        for (int kt = 0; kt < NK - 3; ++kt) {
            CP_WAIT(2);
            __syncthreads();   // tile kt visible; frees stage (kt+3)%4
            COMPUTE_TILE(sb + (uint32_t)(kt & (NSTAGES - 1)) * STAGE_BYTES);
            LOAD_STAGE((kt + 3) & (NSTAGES - 1), kt + 3);
        }
        // peeled tail: kt = NK-3, NK-2, NK-1 (no more loads; taper waits)
        CP_WAIT(2); __syncthreads();
        COMPUTE_TILE(sb + (uint32_t)((NK - 3) & (NSTAGES - 1)) * STAGE_BYTES);
        CP_WAIT(1); __syncthreads();
        COMPUTE_TILE(sb + (uint32_t)((NK - 2) & (NSTAGES - 1)) * STAGE_BYTES);
        CP_WAIT(0); __syncthreads();
        COMPUTE_TILE(sb + (uint32_t)((NK - 1) & (NSTAGES - 1)) * STAGE_BYTES);

        #undef COMPUTE_TILE
        #undef LOAD_STAGE

        // ===== fused epilogue: acc -> smem -> activations -> out =====
        __syncthreads();   // done reading stage buffers; reuse smem for gates
        float* sg = reinterpret_cast<float*>(smem);   // [128][EPITCH]
        int gid = lid >> 2, tig = lid & 3;
        #pragma unroll
        for (int am = 0; am < 2; ++am) {
            #pragma unroll
            for (int bn = 0; bn < 8; ++bn) {
                const float* c = acc[am][bn];
                int row = wm + am * 16 + gid;
                int col = wn + bn * 8 + tig * 2;
                sg[row * EPITCH + col]           = c[0];
                sg[row * EPITCH + col + 1]       = c[1];
                sg[(row + 8) * EPITCH + col]     = c[2];
                sg[(row + 8) * EPITCH + col + 1] = c[3];
            }
        }
        __syncthreads();

        const int BH = BDIM * HDIM;
        #pragma unroll
        for (int i = 0; i < 16; ++i) {
            int idx = tid + i * NTHREADS;   // 128 rows x 32 j
            int row = idx >> 5, lj = idx & 31;
            float4 gv = *reinterpret_cast<const float4*>(&sg[row * EPITCH + lj * 4]);
            int jg = j_base + lj;
            float4 bv = *reinterpret_cast<const float4*>(&g_bias[jg * 4]);
            float fp = gv.x + bv.x, ip = gv.y + bv.y, op = gv.z + bv.z, cp = gv.w + bv.w;
            float ft = 1.0f / (1.0f + expf(-fp));
            float it = 1.0f / (1.0f + expf(-ip));
            float ot = 1.0f / (1.0f + expf(-op));
            float ct = tanhf(cp);
            int m = m0 + row;
            int oidx = m * HDIM + jg;
            float cpv = c_prev[oidx];
            float cn = ft * cpv + it * cpv + g_mask[m] * (it * ct);
            float hn = ot * tanhf(cn);
            out[oidx] = hn;
            if (BH + oidx < n_out)     out[BH + oidx] = cn;
            if (2 * BH + oidx < n_out) out[2 * BH + oidx] = ct;
        }
        __syncthreads();   // epilogue reads done before next tile's cp.async writes
    }
}

// ===================== launcher =====================
extern "C" void kernel_launch(void* const* d_in, const int* in_sizes, int n_in,
                              void* d_out, int out_size) {
    (void)n_in;
    const float* x      = (const float*)d_in[0];
    const float* h_prev = (const float*)d_in[1];
    const float* c_prev = (const float*)d_in[2];
    // d_in[3] = c_prev_tilde_dummy (unused)

    // Input order detection (dict order vs signature order); see round-2 notes.
    const float *W[4], *V[4], *bW[4], *bV[4], *bx[4];
    if (in_sizes[8] > 100000) {
        for (int g = 0; g < 4; ++g) {   // dict order
            W[g]  = (const float*)d_in[4 + 4 * g];
            bW[g] = (const float*)d_in[5 + 4 * g];
            V[g]  = (const float*)d_in[6 + 4 * g];
            bV[g] = (const float*)d_in[7 + 4 * g];
            bx[g] = (const float*)d_in[20 + g];
        }
    } else {
        for (int g = 0; g < 4; ++g) {   // signature order
            W[g]  = (const float*)d_in[4 + 5 * g];
            bW[g] = (const float*)d_in[5 + 5 * g];
            V[g]  = (const float*)d_in[6 + 5 * g];
            bV[g] = (const float*)d_in[7 + 5 * g];
            bx[g] = (const float*)d_in[8 + 5 * g];
        }
    }

    prep_kernel<<<BDIM + NDIM + 16, 256>>>(x, h_prev,
                                           W[0], W[1], W[2], W[3],
                                           V[0], V[1], V[2], V[3],
                                           bW[0], bV[0], bx[0], bW[1], bV[1], bx[1],
                                           bW[2], bV[2], bx[2], bW[3], bV[3], bx[3]);

    cudaFuncSetAttribute(gemm_kernel, cudaFuncAttributeMaxDynamicSharedMemorySize,
                         (int)GEMM_SMEM);
    gemm_kernel<<<GRID_CTAS, NTHREADS, GEMM_SMEM>>>(c_prev, (float*)d_out, out_size);
}